// round 2
// baseline (speedup 1.0000x reference)
#include <cuda_runtime.h>
#include <cuda_bf16.h>

#define N_NODES 100000
#define N_EDGES 3200000
#define N_GRAPHS 256
// DIMS: 38 -> 64 -> 32 -> 16

// ---------------- scratch (static device globals; no allocs) ----------------
__device__ float g_agg0[N_NODES * 38];   // raw-x aggregate (layer 0)
__device__ float g_agg1[N_NODES * 32];   // aggregated y1
__device__ float g_agg2[N_NODES * 16];   // aggregated y2
__device__ float g_h1[N_NODES * 64];     // layer-0 output (tanh)
__device__ float g_h2[N_NODES * 32];     // layer-1 output (tanh)
__device__ float g_y1[N_NODES * 32];     // h1 @ W_rel1^T  (no bias)
__device__ float g_y2[N_NODES * 16];     // h2 @ W_rel2^T  (no bias)
__device__ int   g_src[N_EDGES];
__device__ int   g_dst[N_EDGES];
__device__ float g_pool[N_GRAPHS * 16];
__device__ float g_cnt[N_GRAPHS];
__device__ int   g_ei_is64;
__device__ int   g_b_is64;

// ---------------- dtype detection (int32 vs int64 buffers) ------------------
// edge_index: unsorted values in [0, 1e5). If int64, every high (odd) 32-bit
// word is 0. If int32, the odd words are random values (P(all 64 zero) ~ 0).
// batch_vec: sorted 0..255, so the FRONT is 0 either way; inspect the LAST
// 32-bit word (index N-1): 0 iff int64 (high half of element 49999),
// ~255 != 0 iff int32 (max of sorted array).
__global__ void k_detect(const int* __restrict__ ei_raw,
                         const int* __restrict__ b_raw) {
    int nz = 0;
    #pragma unroll
    for (int i = 0; i < 64; i++) nz |= ei_raw[2 * i + 1];
    g_ei_is64 = (nz == 0) ? 1 : 0;
    g_b_is64 = (b_raw[N_NODES - 1] == 0) ? 1 : 0;
}

// ---------------- convert edge indices to int32 (either source dtype) -------
__global__ void k_convert(const int* __restrict__ ei_raw) {
    int e = blockIdx.x * blockDim.x + threadIdx.x;
    if (e >= N_EDGES) return;
    if (g_ei_is64) {
        g_src[e] = ei_raw[2 * (long long)e];                 // low word (LE)
        g_dst[e] = ei_raw[2 * ((long long)N_EDGES + e)];
    } else {
        g_src[e] = ei_raw[e];
        g_dst[e] = ei_raw[N_EDGES + e];
    }
}

// ---------------- zero all accumulators up front ----------------
__global__ void k_zero_all() {
    long long i = (long long)blockIdx.x * blockDim.x + threadIdx.x;
    long long stride = (long long)gridDim.x * blockDim.x;
    for (long long k = i; k < (long long)N_NODES * 38; k += stride) g_agg0[k] = 0.f;
    for (long long k = i; k < (long long)N_NODES * 32; k += stride) g_agg1[k] = 0.f;
    for (long long k = i; k < (long long)N_NODES * 16; k += stride) g_agg2[k] = 0.f;
    for (long long k = i; k < N_GRAPHS * 16; k += stride) g_pool[k] = 0.f;
    for (long long k = i; k < N_GRAPHS; k += stride) g_cnt[k] = 0.f;
}

// ---------------- layer-0 scatter: agg0[dst] += x[src]  (dim 38) ------------
// One warp per edge.
__global__ void k_scatter0(const float* __restrict__ x) {
    int warp = (blockIdx.x * blockDim.x + threadIdx.x) >> 5;
    int lane = threadIdx.x & 31;
    if (warp >= N_EDGES) return;
    int s = g_src[warp];
    int d = g_dst[warp];
    const float* xs = x + (long long)s * 38;
    float* ad = g_agg0 + (long long)d * 38;
    atomicAdd(&ad[lane], xs[lane]);
    if (lane < 6) atomicAdd(&ad[32 + lane], xs[32 + lane]);
}

// ---------------- layer-1 scatter: agg1[dst] += y1[src] (dim 32) ------------
__global__ void k_scatter1() {
    int warp = (blockIdx.x * blockDim.x + threadIdx.x) >> 5;
    int lane = threadIdx.x & 31;
    if (warp >= N_EDGES) return;
    int s = g_src[warp];
    int d = g_dst[warp];
    atomicAdd(&g_agg1[d * 32 + lane], g_y1[s * 32 + lane]);
}

// ---------------- layer-2 scatter: agg2[dst] += y2[src] (dim 16) ------------
// Two edges per warp.
__global__ void k_scatter2() {
    int warp = (blockIdx.x * blockDim.x + threadIdx.x) >> 5;
    int lane = threadIdx.x & 31;
    int e = warp * 2 + (lane >> 4);
    if (e >= N_EDGES) return;
    int k = lane & 15;
    int s = g_src[e];
    int d = g_dst[e];
    atomicAdd(&g_agg2[d * 16 + k], g_y2[s * 16 + k]);
}

// ---------------- node kernel 0: h1 = tanh(agg0 Wr0^T + b0 + x Wt0^T);
//                  y1 = h1 Wr1^T.  4 nodes/block, 64 threads/node. -----------
__global__ void k_node0(const float* __restrict__ x,
                        const float* __restrict__ Wr0,  // [64,38]
                        const float* __restrict__ b0,   // [64]
                        const float* __restrict__ Wt0,  // [64,38]
                        const float* __restrict__ Wr1)  // [32,64]
{
    __shared__ float sWr0[64 * 38], sWt0[64 * 38], sWr1[32 * 64], sb0[64];
    __shared__ float sa[4][40], sx[4][40], sh[4][64];
    int t = threadIdx.x;
    for (int i = t; i < 64 * 38; i += 256) { sWr0[i] = Wr0[i]; sWt0[i] = Wt0[i]; }
    for (int i = t; i < 32 * 64; i += 256) sWr1[i] = Wr1[i];
    if (t < 64) sb0[t] = b0[t];
    int nbase = blockIdx.x * 4;
    for (int i = t; i < 4 * 38; i += 256) {
        int n2 = i / 38, j = i % 38;
        int nn = nbase + n2;
        if (nn < N_NODES) {
            sa[n2][j] = g_agg0[nn * 38 + j];
            sx[n2][j] = x[(long long)nn * 38 + j];
        }
    }
    __syncthreads();
    int nl = t >> 6, o = t & 63;
    int node = nbase + nl;
    bool valid = node < N_NODES;
    float h = 0.f;
    if (valid) {
        h = sb0[o];
        #pragma unroll
        for (int j = 0; j < 38; j++)
            h += sWr0[o * 38 + j] * sa[nl][j] + sWt0[o * 38 + j] * sx[nl][j];
        h = tanhf(h);
        g_h1[node * 64 + o] = h;
    }
    sh[nl][o] = h;
    __syncthreads();
    if (valid && o < 32) {
        float y = 0.f;
        #pragma unroll
        for (int j = 0; j < 64; j++) y += sWr1[o * 64 + j] * sh[nl][j];
        g_y1[node * 32 + o] = y;
    }
}

// ---------------- node kernel 1: h2 = tanh(agg1 + b1 + h1 Wt1^T);
//                  y2 = h2 Wr2^T.  8 nodes/block, 32 threads/node. -----------
__global__ void k_node1(const float* __restrict__ b1,   // [32]
                        const float* __restrict__ Wt1,  // [32,64]
                        const float* __restrict__ Wr2)  // [16,32]
{
    __shared__ float sWt1[32 * 64], sWr2[16 * 32], sb1[32];
    __shared__ float sh1[8][64], sh2[8][33];
    int t = threadIdx.x;
    for (int i = t; i < 32 * 64; i += 256) sWt1[i] = Wt1[i];
    for (int i = t; i < 16 * 32; i += 256) sWr2[i] = Wr2[i];
    if (t < 32) sb1[t] = b1[t];
    int nbase = blockIdx.x * 8;
    for (int i = t; i < 8 * 64; i += 256) {
        int n2 = i >> 6, j = i & 63;
        int nn = nbase + n2;
        if (nn < N_NODES) sh1[n2][j] = g_h1[nn * 64 + j];
    }
    __syncthreads();
    int nl = t >> 5, o = t & 31;
    int node = nbase + nl;
    float h = 0.f;
    if (node < N_NODES) {
        h = g_agg1[node * 32 + o] + sb1[o];
        #pragma unroll
        for (int j = 0; j < 64; j++) h += sWt1[o * 64 + j] * sh1[nl][j];
        h = tanhf(h);
        g_h2[node * 32 + o] = h;
    }
    sh2[nl][o] = h;
    __syncthreads();
    if (node < N_NODES && o < 16) {
        float y = 0.f;
        #pragma unroll
        for (int j = 0; j < 32; j++) y += sWr2[o * 32 + j] * sh2[nl][j];
        g_y2[node * 16 + o] = y;
    }
}

// ---------------- node kernel 2 + pooling: o = agg2 + b2 + h2 Wt2^T;
//                  pool[g] += o; cnt[g] += 1.  16 nodes/block. ---------------
__global__ void k_node2_pool(const int* __restrict__ batch_raw,
                             const float* __restrict__ b2,   // [16]
                             const float* __restrict__ Wt2)  // [16,32]
{
    __shared__ float sWt2[16 * 32], sb2[16];
    __shared__ float sh2[16][33];
    int t = threadIdx.x;
    for (int i = t; i < 16 * 32; i += 256) sWt2[i] = Wt2[i];
    if (t < 16) sb2[t] = b2[t];
    int nbase = blockIdx.x * 16;
    for (int i = t; i < 16 * 32; i += 256) {
        int n2 = i >> 5, j = i & 31;
        int nn = nbase + n2;
        if (nn < N_NODES) sh2[n2][j] = g_h2[nn * 32 + j];
    }
    __syncthreads();
    int nl = t >> 4, k = t & 15;
    int node = nbase + nl;
    if (node < N_NODES) {
        float o = g_agg2[node * 16 + k] + sb2[k];
        #pragma unroll
        for (int j = 0; j < 32; j++) o += sWt2[k * 32 + j] * sh2[nl][j];
        int g = g_b_is64 ? batch_raw[2 * node] : batch_raw[node];
        atomicAdd(&g_pool[g * 16 + k], o);
        if (k == 0) atomicAdd(&g_cnt[g], 1.0f);
    }
}

// ---------------- final: out = tanh(pool / max(cnt,1)) ----------------------
__global__ void k_final(float* __restrict__ out) {
    int t = blockIdx.x * blockDim.x + threadIdx.x;
    if (t < N_GRAPHS * 16) {
        int g = t >> 4;
        out[t] = tanhf(g_pool[t] / fmaxf(g_cnt[g], 1.0f));
    }
}

extern "C" void kernel_launch(void* const* d_in, const int* in_sizes, int n_in,
                              void* d_out, int out_size) {
    const float* x        = (const float*)d_in[0];
    const int*   ei_raw   = (const int*)d_in[1];   // int32 or int64 (detected)
    const int*   batch_raw= (const int*)d_in[2];   // int32 or int64 (detected)
    const float* Wr0 = (const float*)d_in[3];
    const float* b0  = (const float*)d_in[4];
    const float* Wt0 = (const float*)d_in[5];
    const float* Wr1 = (const float*)d_in[6];
    const float* b1  = (const float*)d_in[7];
    const float* Wt1 = (const float*)d_in[8];
    const float* Wr2 = (const float*)d_in[9];
    const float* b2  = (const float*)d_in[10];
    const float* Wt2 = (const float*)d_in[11];
    float* out = (float*)d_out;

    k_detect<<<1, 1>>>(ei_raw, batch_raw);
    k_convert<<<(N_EDGES + 255) / 256, 256>>>(ei_raw);
    k_zero_all<<<2048, 256>>>();
    // layer 0: aggregate raw x (dim 38), then dense node update (fused with y1)
    k_scatter0<<<(N_EDGES + 7) / 8, 256>>>(x);              // 1 warp/edge
    k_node0<<<(N_NODES + 3) / 4, 256>>>(x, Wr0, b0, Wt0, Wr1);
    // layer 1: aggregate transformed y1 (dim 32)
    k_scatter1<<<(N_EDGES + 7) / 8, 256>>>();
    k_node1<<<(N_NODES + 7) / 8, 256>>>(b1, Wt1, Wr2);
    // layer 2: aggregate transformed y2 (dim 16), fuse node update with pooling
    k_scatter2<<<(N_EDGES + 15) / 16, 256>>>();
    k_node2_pool<<<(N_NODES + 15) / 16, 256>>>(batch_raw, b2, Wt2);
    k_final<<<16, 256>>>(out);
}

// round 4
// speedup vs baseline: 1.4655x; 1.4655x over previous
#include <cuda_runtime.h>
#include <cuda_bf16.h>

#define N_NODES 100000
#define N_EDGES 3200000
#define N_GRAPHS 256
// DIMS: 38 -> 64 -> 32 -> 16

// ---------------- scratch (static device globals; no allocs) ----------------
__device__ float g_x40 [N_NODES * 40];   // x padded to stride 40 (16B aligned)
__device__ float g_agg0[N_NODES * 40];   // raw-x aggregate, padded stride 40
__device__ float g_agg1[N_NODES * 32];   // aggregated y1
__device__ float g_agg2[N_NODES * 16];   // aggregated y2
__device__ float g_h1[N_NODES * 64];     // layer-0 output (tanh)
__device__ float g_h2[N_NODES * 32];     // layer-1 output (tanh)
__device__ float g_y1[N_NODES * 32];     // h1 @ W_rel1^T  (no bias)
__device__ float g_y2[N_NODES * 16];     // h2 @ W_rel2^T  (no bias)
__device__ int   g_src[N_EDGES];
__device__ int   g_dst[N_EDGES];
__device__ float g_pool[N_GRAPHS * 16];
__device__ float g_cnt[N_GRAPHS];
__device__ int   g_ei_is64;
__device__ int   g_b_is64;

__device__ __forceinline__ void red_add_v4(float* addr, float4 v) {
    asm volatile("red.global.add.v4.f32 [%0], {%1,%2,%3,%4};"
                 :: "l"(addr), "f"(v.x), "f"(v.y), "f"(v.z), "f"(v.w)
                 : "memory");
}

// ---------------- dtype detection (int32 vs int64 buffers) ------------------
// edge_index values are random in [0,1e5): if stored as int64, all odd 32-bit
// words of the first 64 elements are zero; if int32 they are random nonzero.
// batch_vec is sorted 0..255: last 32-bit word is 0 iff int64.
__global__ void k_detect(const int* __restrict__ ei_raw,
                         const int* __restrict__ b_raw) {
    int nz = 0;
    #pragma unroll
    for (int i = 0; i < 64; i++) nz |= ei_raw[2 * i + 1];
    g_ei_is64 = (nz == 0) ? 1 : 0;
    g_b_is64 = (b_raw[N_NODES - 1] == 0) ? 1 : 0;
}

// ---------------- convert edge indices to int32 (either source dtype) -------
__global__ void k_convert(const int* __restrict__ ei_raw) {
    int e = blockIdx.x * blockDim.x + threadIdx.x;
    if (e >= N_EDGES) return;
    if (g_ei_is64) {
        g_src[e] = ei_raw[2 * (long long)e];                 // low word (LE)
        g_dst[e] = ei_raw[2 * ((long long)N_EDGES + e)];
    } else {
        g_src[e] = ei_raw[e];
        g_dst[e] = ei_raw[N_EDGES + e];
    }
}

// ---------------- zero accumulators + pack x into stride-40 -----------------
__global__ void k_zero_pack(const float* __restrict__ x) {
    long long i = (long long)blockIdx.x * blockDim.x + threadIdx.x;
    long long stride = (long long)gridDim.x * blockDim.x;
    for (long long k = i; k < (long long)N_NODES * 40; k += stride) {
        g_agg0[k] = 0.f;
        int j = (int)(k % 40);
        g_x40[k] = (j < 38) ? x[(k / 40) * 38 + j] : 0.f;
    }
    for (long long k = i; k < (long long)N_NODES * 32; k += stride) g_agg1[k] = 0.f;
    for (long long k = i; k < (long long)N_NODES * 16; k += stride) g_agg2[k] = 0.f;
    for (long long k = i; k < N_GRAPHS * 16; k += stride) g_pool[k] = 0.f;
    for (long long k = i; k < N_GRAPHS; k += stride) g_cnt[k] = 0.f;
}

// ---------------- layer-0 scatter: agg0[dst] += x40[src]  (10 x v4) ---------
__global__ void k_scatter0() {
    long long idx = (long long)blockIdx.x * blockDim.x + threadIdx.x;
    if (idx >= (long long)N_EDGES * 10) return;
    int e = (int)(idx / 10);
    int c = (int)(idx - (long long)e * 10);
    int s = g_src[e];
    int d = g_dst[e];
    float4 v = *(const float4*)&g_x40[s * 40 + c * 4];
    red_add_v4(&g_agg0[d * 40 + c * 4], v);
}

// ---------------- layer-1 scatter: agg1[dst] += y1[src] (8 x v4) ------------
__global__ void k_scatter1() {
    long long idx = (long long)blockIdx.x * blockDim.x + threadIdx.x;
    if (idx >= (long long)N_EDGES * 8) return;
    int e = (int)(idx >> 3);
    int c = (int)(idx & 7);
    int s = g_src[e];
    int d = g_dst[e];
    float4 v = *(const float4*)&g_y1[s * 32 + c * 4];
    red_add_v4(&g_agg1[d * 32 + c * 4], v);
}

// ---------------- layer-2 scatter: agg2[dst] += y2[src] (4 x v4) ------------
__global__ void k_scatter2() {
    long long idx = (long long)blockIdx.x * blockDim.x + threadIdx.x;
    if (idx >= (long long)N_EDGES * 4) return;
    int e = (int)(idx >> 2);
    int c = (int)(idx & 3);
    int s = g_src[e];
    int d = g_dst[e];
    float4 v = *(const float4*)&g_y2[s * 16 + c * 4];
    red_add_v4(&g_agg2[d * 16 + c * 4], v);
}

// ---------------- node kernel 0 (persistent): h1 = tanh(agg0 Wr0^T + b0 +
//                  x Wt0^T); y1 = h1 Wr1^T.  4 nodes/iter, 64 thr/node. ------
__global__ void k_node0(const float* __restrict__ Wr0,  // [64,38]
                        const float* __restrict__ b0,   // [64]
                        const float* __restrict__ Wt0,  // [64,38]
                        const float* __restrict__ Wr1)  // [32,64]
{
    __shared__ float sWr0[64 * 38], sWt0[64 * 38], sWr1[32 * 64], sb0[64];
    __shared__ float sa[4][40], sx[4][40], sh[4][64];
    int t = threadIdx.x;
    for (int i = t; i < 64 * 38; i += 256) { sWr0[i] = Wr0[i]; sWt0[i] = Wt0[i]; }
    for (int i = t; i < 32 * 64; i += 256) sWr1[i] = Wr1[i];
    if (t < 64) sb0[t] = b0[t];
    __syncthreads();
    int nl = t >> 6, o = t & 63;
    for (int nbase = blockIdx.x * 4; nbase < N_NODES; nbase += gridDim.x * 4) {
        for (int i = t; i < 4 * 40; i += 256) {
            int n2 = i / 40, j = i % 40;
            int nn = nbase + n2;
            if (nn < N_NODES && j < 38) {
                sa[n2][j] = g_agg0[nn * 40 + j];
                sx[n2][j] = g_x40[nn * 40 + j];
            }
        }
        __syncthreads();
        int node = nbase + nl;
        bool valid = node < N_NODES;
        float h = 0.f;
        if (valid) {
            h = sb0[o];
            #pragma unroll
            for (int j = 0; j < 38; j++)
                h += sWr0[o * 38 + j] * sa[nl][j] + sWt0[o * 38 + j] * sx[nl][j];
            h = tanhf(h);
            g_h1[node * 64 + o] = h;
        }
        sh[nl][o] = h;
        __syncthreads();
        if (valid && o < 32) {
            float y = 0.f;
            #pragma unroll
            for (int j = 0; j < 64; j++) y += sWr1[o * 64 + j] * sh[nl][j];
            g_y1[node * 32 + o] = y;
        }
        __syncthreads();
    }
}

// ---------------- node kernel 1 (persistent): h2 = tanh(agg1 + b1 + h1 Wt1^T);
//                  y2 = h2 Wr2^T.  8 nodes/iter, 32 thr/node. ----------------
__global__ void k_node1(const float* __restrict__ b1,   // [32]
                        const float* __restrict__ Wt1,  // [32,64]
                        const float* __restrict__ Wr2)  // [16,32]
{
    __shared__ float sWt1[32 * 64], sWr2[16 * 32], sb1[32];
    __shared__ float sh1[8][64], sh2[8][33];
    int t = threadIdx.x;
    for (int i = t; i < 32 * 64; i += 256) sWt1[i] = Wt1[i];
    for (int i = t; i < 16 * 32; i += 256) sWr2[i] = Wr2[i];
    if (t < 32) sb1[t] = b1[t];
    __syncthreads();
    int nl = t >> 5, o = t & 31;
    for (int nbase = blockIdx.x * 8; nbase < N_NODES; nbase += gridDim.x * 8) {
        for (int i = t; i < 8 * 64; i += 256) {
            int n2 = i >> 6, j = i & 63;
            int nn = nbase + n2;
            if (nn < N_NODES) sh1[n2][j] = g_h1[nn * 64 + j];
        }
        __syncthreads();
        int node = nbase + nl;
        float h = 0.f;
        if (node < N_NODES) {
            h = g_agg1[node * 32 + o] + sb1[o];
            #pragma unroll
            for (int j = 0; j < 64; j++) h += sWt1[o * 64 + j] * sh1[nl][j];
            h = tanhf(h);
            g_h2[node * 32 + o] = h;
        }
        sh2[nl][o] = h;
        __syncthreads();
        if (node < N_NODES && o < 16) {
            float y = 0.f;
            #pragma unroll
            for (int j = 0; j < 32; j++) y += sWr2[o * 32 + j] * sh2[nl][j];
            g_y2[node * 16 + o] = y;
        }
        __syncthreads();
    }
}

// ---------------- node kernel 2 + pooling (persistent) ----------------------
__global__ void k_node2_pool(const int* __restrict__ batch_raw,
                             const float* __restrict__ b2,   // [16]
                             const float* __restrict__ Wt2)  // [16,32]
{
    __shared__ float sWt2[16 * 32], sb2[16];
    __shared__ float sh2[16][33];
    int t = threadIdx.x;
    for (int i = t; i < 16 * 32; i += 256) sWt2[i] = Wt2[i];
    if (t < 16) sb2[t] = b2[t];
    __syncthreads();
    int nl = t >> 4, k = t & 15;
    for (int nbase = blockIdx.x * 16; nbase < N_NODES; nbase += gridDim.x * 16) {
        for (int i = t; i < 16 * 32; i += 256) {
            int n2 = i >> 5, j = i & 31;
            int nn = nbase + n2;
            if (nn < N_NODES) sh2[n2][j] = g_h2[nn * 32 + j];
        }
        __syncthreads();
        int node = nbase + nl;
        if (node < N_NODES) {
            float o = g_agg2[node * 16 + k] + sb2[k];
            #pragma unroll
            for (int j = 0; j < 32; j++) o += sWt2[k * 32 + j] * sh2[nl][j];
            int g = g_b_is64 ? batch_raw[2 * node] : batch_raw[node];
            atomicAdd(&g_pool[g * 16 + k], o);
            if (k == 0) atomicAdd(&g_cnt[g], 1.0f);
        }
        __syncthreads();
    }
}

// ---------------- final: out = tanh(pool / max(cnt,1)) ----------------------
__global__ void k_final(float* __restrict__ out) {
    int t = blockIdx.x * blockDim.x + threadIdx.x;
    if (t < N_GRAPHS * 16) {
        int g = t >> 4;
        out[t] = tanhf(g_pool[t] / fmaxf(g_cnt[g], 1.0f));
    }
}

extern "C" void kernel_launch(void* const* d_in, const int* in_sizes, int n_in,
                              void* d_out, int out_size) {
    const float* x         = (const float*)d_in[0];
    const int*   ei_raw    = (const int*)d_in[1];
    const int*   batch_raw = (const int*)d_in[2];
    const float* Wr0 = (const float*)d_in[3];
    const float* b0  = (const float*)d_in[4];
    const float* Wt0 = (const float*)d_in[5];
    const float* Wr1 = (const float*)d_in[6];
    const float* b1  = (const float*)d_in[7];
    const float* Wt1 = (const float*)d_in[8];
    const float* Wr2 = (const float*)d_in[9];
    const float* b2  = (const float*)d_in[10];
    const float* Wt2 = (const float*)d_in[11];
    float* out = (float*)d_out;

    k_detect<<<1, 1>>>(ei_raw, batch_raw);
    k_convert<<<(N_EDGES + 255) / 256, 256>>>(ei_raw);
    k_zero_pack<<<2048, 256>>>(x);
    // layer 0: aggregate padded raw x (10 float4 REDs / edge)
    k_scatter0<<<(int)(((long long)N_EDGES * 10 + 255) / 256), 256>>>();
    k_node0<<<512, 256>>>(Wr0, b0, Wt0, Wr1);
    // layer 1: aggregate transformed y1 (8 float4 REDs / edge)
    k_scatter1<<<(int)(((long long)N_EDGES * 8 + 255) / 256), 256>>>();
    k_node1<<<512, 256>>>(b1, Wt1, Wr2);
    // layer 2: aggregate transformed y2 (4 float4 REDs / edge)
    k_scatter2<<<(int)(((long long)N_EDGES * 4 + 255) / 256), 256>>>();
    k_node2_pool<<<512, 256>>>(batch_raw, b2, Wt2);
    k_final<<<16, 256>>>(out);
}

// round 5
// speedup vs baseline: 2.5602x; 1.7470x over previous
#include <cuda_runtime.h>
#include <cuda_bf16.h>

#define N_NODES 100000
#define N_EDGES 3200000
#define N_GRAPHS 256
// DIMS: 38 -> 64 -> 32 -> 16

// ---------------- scratch (static device globals; no allocs) ----------------
__device__ float g_x40 [N_NODES * 40];   // x padded to stride 40 (16B aligned)
__device__ float g_agg0[N_NODES * 40];   // raw-x aggregate, padded stride 40
__device__ float g_agg1[N_NODES * 32];   // aggregated y1
__device__ float g_agg2[N_NODES * 16];   // aggregated y2
__device__ float g_h1[N_NODES * 64];     // layer-0 output (tanh)
__device__ float g_h2[N_NODES * 32];     // layer-1 output (tanh)
__device__ float g_y1[N_NODES * 32];     // h1 @ W_rel1^T
__device__ float g_y2[N_NODES * 16];     // h2 @ W_rel2^T
__device__ int   g_src[N_EDGES];
__device__ int   g_dst[N_EDGES];
__device__ float g_pool[N_GRAPHS * 16];
__device__ float g_cnt[N_GRAPHS];
__device__ int   g_ei_is64;
__device__ int   g_b_is64;

__device__ __forceinline__ void red_add_v4(float* addr, float4 v) {
    asm volatile("red.global.add.v4.f32 [%0], {%1,%2,%3,%4};"
                 :: "l"(addr), "f"(v.x), "f"(v.y), "f"(v.z), "f"(v.w)
                 : "memory");
}

// ---------------- dtype detection (int32 vs int64 buffers) ------------------
__global__ void k_detect(const int* __restrict__ ei_raw,
                         const int* __restrict__ b_raw) {
    int nz = 0;
    #pragma unroll
    for (int i = 0; i < 64; i++) nz |= ei_raw[2 * i + 1];
    g_ei_is64 = (nz == 0) ? 1 : 0;
    g_b_is64 = (b_raw[N_NODES - 1] == 0) ? 1 : 0;
}

// ---------------- fused prep: convert indices + zero + pack x ---------------
__global__ void k_prep(const float* __restrict__ x,
                       const int* __restrict__ ei_raw) {
    long long i = (long long)blockIdx.x * blockDim.x + threadIdx.x;
    long long stride = (long long)gridDim.x * blockDim.x;
    int is64 = g_ei_is64;
    for (long long e = i; e < N_EDGES; e += stride) {
        if (is64) {
            g_src[e] = ei_raw[2 * e];
            g_dst[e] = ei_raw[2 * ((long long)N_EDGES + e)];
        } else {
            g_src[e] = ei_raw[e];
            g_dst[e] = ei_raw[N_EDGES + e];
        }
    }
    for (long long k = i; k < (long long)N_NODES * 40; k += stride) {
        g_agg0[k] = 0.f;
        int j = (int)(k % 40);
        g_x40[k] = (j < 38) ? x[(k / 40) * 38 + j] : 0.f;
    }
    for (long long k = i; k < (long long)N_NODES * 32; k += stride) g_agg1[k] = 0.f;
    for (long long k = i; k < (long long)N_NODES * 16; k += stride) g_agg2[k] = 0.f;
    for (long long k = i; k < N_GRAPHS * 16; k += stride) g_pool[k] = 0.f;
    for (long long k = i; k < N_GRAPHS; k += stride) g_cnt[k] = 0.f;
}

// ---------------- layer-0 scatter: agg0[dst] += x40[src]  (10 x v4) ---------
__global__ void k_scatter0() {
    long long idx = (long long)blockIdx.x * blockDim.x + threadIdx.x;
    if (idx >= (long long)N_EDGES * 10) return;
    int e = (int)(idx / 10);
    int c = (int)(idx - (long long)e * 10);
    int s = g_src[e];
    int d = g_dst[e];
    float4 v = *(const float4*)&g_x40[s * 40 + c * 4];
    red_add_v4(&g_agg0[d * 40 + c * 4], v);
}

// ---------------- layer-1 scatter: agg1[dst] += y1[src] (8 x v4) ------------
__global__ void k_scatter1() {
    long long idx = (long long)blockIdx.x * blockDim.x + threadIdx.x;
    if (idx >= (long long)N_EDGES * 8) return;
    int e = (int)(idx >> 3);
    int c = (int)(idx & 7);
    int s = g_src[e];
    int d = g_dst[e];
    float4 v = *(const float4*)&g_y1[s * 32 + c * 4];
    red_add_v4(&g_agg1[d * 32 + c * 4], v);
}

// ---------------- layer-2 scatter: agg2[dst] += y2[src] (4 x v4) ------------
__global__ void k_scatter2() {
    long long idx = (long long)blockIdx.x * blockDim.x + threadIdx.x;
    if (idx >= (long long)N_EDGES * 4) return;
    int e = (int)(idx >> 2);
    int c = (int)(idx & 3);
    int s = g_src[e];
    int d = g_dst[e];
    float4 v = *(const float4*)&g_y2[s * 16 + c * 4];
    red_add_v4(&g_agg2[d * 16 + c * 4], v);
}

// ---------------- node kernel 0 (persistent, register weights) --------------
// thread t: output o = t&63, node slot nl = t>>6 (4 nodes/iter).
// h1 = tanh(agg0.Wr0^T + b0 + x.Wt0^T); y1 = h1.Wr1^T (j-split partials).
__global__ void k_node0(const float* __restrict__ Wr0,  // [64,38]
                        const float* __restrict__ b0,   // [64]
                        const float* __restrict__ Wt0,  // [64,38]
                        const float* __restrict__ Wr1)  // [32,64]
{
    int t = threadIdx.x;
    int o = t & 63, nl = t >> 6;
    // register weights (padded to 40 with zeros)
    float wr[40], wt[40];
    #pragma unroll
    for (int j = 0; j < 40; j++) {
        wr[j] = (j < 38) ? Wr0[o * 38 + j] : 0.f;
        wt[j] = (j < 38) ? Wt0[o * 38 + j] : 0.f;
    }
    float bias = b0[o];
    // y1 half-row: thread o<32 covers j 0..31 of row o; o>=32 covers j 32..63 of row o-32
    int oo = o & 31, jb = (o < 32) ? 0 : 32;
    float w1[32];
    #pragma unroll
    for (int jj = 0; jj < 32; jj++) w1[jj] = Wr1[oo * 64 + jb + jj];

    __shared__ float4 sa4[4][10], sx4[4][10];
    __shared__ float  sh[4][64];
    __shared__ float  sp[4][64];

    for (int nbase = blockIdx.x * 4; nbase < N_NODES; nbase += gridDim.x * 4) {
        // stage activations: 4 nodes x 10 float4 x 2 arrays
        for (int i = t; i < 80; i += 256) {
            int n2 = i / 20, r = i % 20;
            int nn = nbase + n2;
            if (nn < N_NODES) {
                if (r < 10) sa4[n2][r] = *(const float4*)&g_agg0[nn * 40 + r * 4];
                else        sx4[n2][r - 10] = *(const float4*)&g_x40[nn * 40 + (r - 10) * 4];
            }
        }
        __syncthreads();
        int node = nbase + nl;
        bool valid = node < N_NODES;
        float h = bias;
        #pragma unroll
        for (int c = 0; c < 10; c++) {
            float4 a = sa4[nl][c], xv = sx4[nl][c];
            h += wr[4 * c + 0] * a.x + wr[4 * c + 1] * a.y + wr[4 * c + 2] * a.z + wr[4 * c + 3] * a.w
               + wt[4 * c + 0] * xv.x + wt[4 * c + 1] * xv.y + wt[4 * c + 2] * xv.z + wt[4 * c + 3] * xv.w;
        }
        h = tanhf(h);
        if (valid) g_h1[node * 64 + o] = h;
        sh[nl][o] = h;
        __syncthreads();
        // y1 partials: each thread 32 FMAs over its j-half
        float p = 0.f;
        #pragma unroll
        for (int c = 0; c < 8; c++) {
            float4 hv = *(const float4*)&sh[nl][jb + c * 4];
            p += w1[4 * c + 0] * hv.x + w1[4 * c + 1] * hv.y + w1[4 * c + 2] * hv.z + w1[4 * c + 3] * hv.w;
        }
        sp[nl][o] = p;
        __syncthreads();
        if (valid && o < 32)
            g_y1[node * 32 + o] = sp[nl][o] + sp[nl][o + 32];
        __syncthreads();
    }
}

// ---------------- node kernel 1 (persistent, register weights) --------------
// thread t: o = t&31 (one warp per node), nl = t>>5 (8 nodes/iter).
// h2 = tanh(agg1 + b1 + h1.Wt1^T); y2 = h2.Wr2^T via shfl-combined partials.
__global__ void k_node1(const float* __restrict__ b1,   // [32]
                        const float* __restrict__ Wt1,  // [32,64]
                        const float* __restrict__ Wr2)  // [16,32]
{
    int t = threadIdx.x;
    int o = t & 31, nl = t >> 5;
    float wt1[64];
    #pragma unroll
    for (int j = 0; j < 64; j++) wt1[j] = Wt1[o * 64 + j];
    float bias = b1[o];
    int oo = o & 15, jb = (o < 16) ? 0 : 16;
    float w2[16];
    #pragma unroll
    for (int jj = 0; jj < 16; jj++) w2[jj] = Wr2[oo * 32 + jb + jj];

    __shared__ float sh1[8][64];
    __shared__ float sh2[8][32];

    for (int nbase = blockIdx.x * 8; nbase < N_NODES; nbase += gridDim.x * 8) {
        for (int i = t; i < 128; i += 256) {
            int n2 = i >> 4, r = i & 15;
            int nn = nbase + n2;
            if (nn < N_NODES)
                *(float4*)&sh1[n2][r * 4] = *(const float4*)&g_h1[nn * 64 + r * 4];
        }
        __syncthreads();
        int node = nbase + nl;
        bool valid = node < N_NODES;
        float h = bias;
        if (valid) h += g_agg1[node * 32 + o];
        #pragma unroll
        for (int c = 0; c < 16; c++) {
            float4 hv = *(const float4*)&sh1[nl][c * 4];
            h += wt1[4 * c + 0] * hv.x + wt1[4 * c + 1] * hv.y + wt1[4 * c + 2] * hv.z + wt1[4 * c + 3] * hv.w;
        }
        h = tanhf(h);
        if (valid) g_h2[node * 32 + o] = h;
        sh2[nl][o] = h;
        __syncwarp();
        // y2 partials over j-half, combine across half-warps
        float p = 0.f;
        #pragma unroll
        for (int c = 0; c < 4; c++) {
            float4 hv = *(const float4*)&sh2[nl][jb + c * 4];
            p += w2[4 * c + 0] * hv.x + w2[4 * c + 1] * hv.y + w2[4 * c + 2] * hv.z + w2[4 * c + 3] * hv.w;
        }
        float other = __shfl_down_sync(0xffffffffu, p, 16);
        if (valid && o < 16)
            g_y2[node * 16 + o] = p + other;
        __syncthreads();
    }
}

// ---------------- node kernel 2 + pooling (persistent, register weights) ----
// thread t: o = t&15, nl = t>>4 (16 nodes/iter).
__global__ void k_node2_pool(const int* __restrict__ batch_raw,
                             const float* __restrict__ b2,   // [16]
                             const float* __restrict__ Wt2)  // [16,32]
{
    int t = threadIdx.x;
    int o = t & 15, nl = t >> 4;
    float wt2[32];
    #pragma unroll
    for (int j = 0; j < 32; j++) wt2[j] = Wt2[o * 32 + j];
    float bias = b2[o];
    int b_is64 = g_b_is64;

    __shared__ float sh2[16][32];

    for (int nbase = blockIdx.x * 16; nbase < N_NODES; nbase += gridDim.x * 16) {
        for (int i = t; i < 128; i += 256) {
            int n2 = i >> 3, r = i & 7;
            int nn = nbase + n2;
            if (nn < N_NODES)
                *(float4*)&sh2[n2][r * 4] = *(const float4*)&g_h2[nn * 32 + r * 4];
        }
        __syncthreads();
        int node = nbase + nl;
        if (node < N_NODES) {
            float acc = bias + g_agg2[node * 16 + o];
            #pragma unroll
            for (int c = 0; c < 8; c++) {
                float4 hv = *(const float4*)&sh2[nl][c * 4];
                acc += wt2[4 * c + 0] * hv.x + wt2[4 * c + 1] * hv.y + wt2[4 * c + 2] * hv.z + wt2[4 * c + 3] * hv.w;
            }
            int g = b_is64 ? batch_raw[2 * node] : batch_raw[node];
            atomicAdd(&g_pool[g * 16 + o], acc);
            if (o == 0) atomicAdd(&g_cnt[g], 1.0f);
        }
        __syncthreads();
    }
}

// ---------------- final: out = tanh(pool / max(cnt,1)) ----------------------
__global__ void k_final(float* __restrict__ out) {
    int t = blockIdx.x * blockDim.x + threadIdx.x;
    if (t < N_GRAPHS * 16) {
        int g = t >> 4;
        out[t] = tanhf(g_pool[t] / fmaxf(g_cnt[g], 1.0f));
    }
}

extern "C" void kernel_launch(void* const* d_in, const int* in_sizes, int n_in,
                              void* d_out, int out_size) {
    const float* x         = (const float*)d_in[0];
    const int*   ei_raw    = (const int*)d_in[1];
    const int*   batch_raw = (const int*)d_in[2];
    const float* Wr0 = (const float*)d_in[3];
    const float* b0  = (const float*)d_in[4];
    const float* Wt0 = (const float*)d_in[5];
    const float* Wr1 = (const float*)d_in[6];
    const float* b1  = (const float*)d_in[7];
    const float* Wt1 = (const float*)d_in[8];
    const float* Wr2 = (const float*)d_in[9];
    const float* b2  = (const float*)d_in[10];
    const float* Wt2 = (const float*)d_in[11];
    float* out = (float*)d_out;

    k_detect<<<1, 1>>>(ei_raw, batch_raw);
    k_prep<<<2048, 256>>>(x, ei_raw);
    k_scatter0<<<(int)(((long long)N_EDGES * 10 + 255) / 256), 256>>>();
    k_node0<<<296, 256>>>(Wr0, b0, Wt0, Wr1);
    k_scatter1<<<(int)(((long long)N_EDGES * 8 + 255) / 256), 256>>>();
    k_node1<<<296, 256>>>(b1, Wt1, Wr2);
    k_scatter2<<<(int)(((long long)N_EDGES * 4 + 255) / 256), 256>>>();
    k_node2_pool<<<296, 256>>>(batch_raw, b2, Wt2);
    k_final<<<16, 256>>>(out);
}

// round 7
// speedup vs baseline: 2.8391x; 1.1089x over previous
#include <cuda_runtime.h>
#include <cuda_bf16.h>

#define N_NODES 100000
#define N_EDGES 3200000
#define N_GRAPHS 256
// DIMS: 38 -> 64 -> 32 -> 16

// ---------------- scratch (static device globals; no allocs) ----------------
__device__ float g_x40 [N_NODES * 40];
__device__ float g_agg0[N_NODES * 40];
__device__ float g_agg1[N_NODES * 32];
__device__ float g_agg2[N_NODES * 16];
__device__ float g_h1[N_NODES * 64];
__device__ float g_h2[N_NODES * 32];
__device__ float g_y1[N_NODES * 32];
__device__ float g_y2[N_NODES * 16];
__device__ int   g_src[N_EDGES];
__device__ int   g_dst[N_EDGES];
__device__ float g_pool[N_GRAPHS * 16];
__device__ float g_cnt[N_GRAPHS];
__device__ int   g_ei_is64;
__device__ int   g_b_is64;

__device__ __forceinline__ void red_add_v4(float* addr, float4 v) {
    asm volatile("red.global.add.v4.f32 [%0], {%1,%2,%3,%4};"
                 :: "l"(addr), "f"(v.x), "f"(v.y), "f"(v.z), "f"(v.w)
                 : "memory");
}

// ---------------- dtype detection (int32 vs int64 buffers) ------------------
__global__ void k_detect(const int* __restrict__ ei_raw,
                         const int* __restrict__ b_raw) {
    int nz = 0;
    #pragma unroll
    for (int i = 0; i < 64; i++) nz |= ei_raw[2 * i + 1];
    g_ei_is64 = (nz == 0) ? 1 : 0;
    g_b_is64 = (b_raw[N_NODES - 1] == 0) ? 1 : 0;
}

// ---------------- fused prep: convert indices + zero + pack x ---------------
__global__ void k_prep(const float* __restrict__ x,
                       const int* __restrict__ ei_raw) {
    long long i = (long long)blockIdx.x * blockDim.x + threadIdx.x;
    long long stride = (long long)gridDim.x * blockDim.x;
    int is64 = g_ei_is64;
    for (long long e = i; e < N_EDGES; e += stride) {
        if (is64) {
            g_src[e] = ei_raw[2 * e];
            g_dst[e] = ei_raw[2 * ((long long)N_EDGES + e)];
        } else {
            g_src[e] = ei_raw[e];
            g_dst[e] = ei_raw[N_EDGES + e];
        }
    }
    for (long long k = i; k < (long long)N_NODES * 40; k += stride) {
        g_agg0[k] = 0.f;
        int j = (int)(k % 40);
        g_x40[k] = (j < 38) ? x[(k / 40) * 38 + j] : 0.f;
    }
    for (long long k = i; k < (long long)N_NODES * 32; k += stride) g_agg1[k] = 0.f;
    for (long long k = i; k < (long long)N_NODES * 16; k += stride) g_agg2[k] = 0.f;
    for (long long k = i; k < N_GRAPHS * 16; k += stride) g_pool[k] = 0.f;
    for (long long k = i; k < N_GRAPHS; k += stride) g_cnt[k] = 0.f;
}

// ---------------- scatters (unchanged; at REDG-lane floor) ------------------
__global__ void k_scatter0() {
    long long idx = (long long)blockIdx.x * blockDim.x + threadIdx.x;
    if (idx >= (long long)N_EDGES * 10) return;
    int e = (int)(idx / 10);
    int c = (int)(idx - (long long)e * 10);
    int s = g_src[e];
    int d = g_dst[e];
    float4 v = *(const float4*)&g_x40[s * 40 + c * 4];
    red_add_v4(&g_agg0[d * 40 + c * 4], v);
}

__global__ void k_scatter1() {
    long long idx = (long long)blockIdx.x * blockDim.x + threadIdx.x;
    if (idx >= (long long)N_EDGES * 8) return;
    int e = (int)(idx >> 3);
    int c = (int)(idx & 7);
    int s = g_src[e];
    int d = g_dst[e];
    float4 v = *(const float4*)&g_y1[s * 32 + c * 4];
    red_add_v4(&g_agg1[d * 32 + c * 4], v);
}

__global__ void k_scatter2() {
    long long idx = (long long)blockIdx.x * blockDim.x + threadIdx.x;
    if (idx >= (long long)N_EDGES * 4) return;
    int e = (int)(idx >> 2);
    int c = (int)(idx & 3);
    int s = g_src[e];
    int d = g_dst[e];
    float4 v = *(const float4*)&g_y2[s * 16 + c * 4];
    red_add_v4(&g_agg2[d * 16 + c * 4], v);
}

// ---------------- node kernel 0: 16 nodes/iter, ILP=4 -----------------------
// thread: o = t&63 (output), sl = t>>6 (4 slots); node nl = sl + 4q, q<4.
__global__ void k_node0(const float* __restrict__ Wr0,  // [64,38]
                        const float* __restrict__ b0,   // [64]
                        const float* __restrict__ Wt0,  // [64,38]
                        const float* __restrict__ Wr1)  // [32,64]
{
    int t = threadIdx.x;
    int o = t & 63, sl = t >> 6;
    float wr[40], wt[40];
    #pragma unroll
    for (int j = 0; j < 40; j++) {
        wr[j] = (j < 38) ? Wr0[o * 38 + j] : 0.f;
        wt[j] = (j < 38) ? Wt0[o * 38 + j] : 0.f;
    }
    float bias = b0[o];
    int oo = o & 31, jb = (o < 32) ? 0 : 32;

    __shared__ float  sW1[32 * 65];          // Wr1 [32x64] row stride 65
    __shared__ float4 sa4[16][10], sx4[16][10];
    __shared__ float  sh[16][64];
    __shared__ float  sp[16][64];
    for (int i = t; i < 32 * 64; i += 256) sW1[(i >> 6) * 65 + (i & 63)] = Wr1[i];
    __syncthreads();

    for (int nbase = blockIdx.x * 16; nbase < N_NODES; nbase += gridDim.x * 16) {
        for (int i = t; i < 320; i += 256) {
            int n2 = i / 20, r = i % 20;
            int nn = nbase + n2;
            if (nn < N_NODES) {
                if (r < 10) sa4[n2][r] = *(const float4*)&g_agg0[nn * 40 + r * 4];
                else        sx4[n2][r - 10] = *(const float4*)&g_x40[nn * 40 + (r - 10) * 4];
            }
        }
        __syncthreads();
        float h0 = bias, h1v = bias, h2v = bias, h3 = bias;
        #pragma unroll
        for (int c = 0; c < 10; c++) {
            float w0 = wr[4*c+0], w1_ = wr[4*c+1], w2_ = wr[4*c+2], w3 = wr[4*c+3];
            float u0 = wt[4*c+0], u1 = wt[4*c+1], u2 = wt[4*c+2], u3 = wt[4*c+3];
            float4 a, xv;
            a = sa4[sl][c];      xv = sx4[sl][c];
            h0 += w0*a.x + w1_*a.y + w2_*a.z + w3*a.w + u0*xv.x + u1*xv.y + u2*xv.z + u3*xv.w;
            a = sa4[sl+4][c];    xv = sx4[sl+4][c];
            h1v += w0*a.x + w1_*a.y + w2_*a.z + w3*a.w + u0*xv.x + u1*xv.y + u2*xv.z + u3*xv.w;
            a = sa4[sl+8][c];    xv = sx4[sl+8][c];
            h2v += w0*a.x + w1_*a.y + w2_*a.z + w3*a.w + u0*xv.x + u1*xv.y + u2*xv.z + u3*xv.w;
            a = sa4[sl+12][c];   xv = sx4[sl+12][c];
            h3 += w0*a.x + w1_*a.y + w2_*a.z + w3*a.w + u0*xv.x + u1*xv.y + u2*xv.z + u3*xv.w;
        }
        h0 = tanhf(h0); h1v = tanhf(h1v); h2v = tanhf(h2v); h3 = tanhf(h3);
        float hq[4] = {h0, h1v, h2v, h3};
        #pragma unroll
        for (int q = 0; q < 4; q++) {
            int nl = sl + 4 * q, node = nbase + nl;
            if (node < N_NODES) g_h1[node * 64 + o] = hq[q];
            sh[nl][o] = hq[q];
        }
        __syncthreads();
        #pragma unroll
        for (int q = 0; q < 4; q++) {
            int nl = sl + 4 * q;
            float p = 0.f;
            #pragma unroll
            for (int c = 0; c < 8; c++) {
                float4 hv = *(const float4*)&sh[nl][jb + c * 4];
                const float* wrow = &sW1[oo * 65 + jb + c * 4];
                p += wrow[0]*hv.x + wrow[1]*hv.y + wrow[2]*hv.z + wrow[3]*hv.w;
            }
            sp[nl][o] = p;
        }
        __syncthreads();
        if (o < 32) {
            #pragma unroll
            for (int q = 0; q < 4; q++) {
                int nl = sl + 4 * q, node = nbase + nl;
                if (node < N_NODES) g_y1[node * 32 + o] = sp[nl][o] + sp[nl][o + 32];
            }
        }
        __syncthreads();
    }
}

// ---------------- node kernel 1: 32 nodes/iter, ILP=4 -----------------------
// thread: o = t&31 (warp per node-slot), sl = t>>5 (8 slots); nl = sl + 8q.
__global__ void k_node1(const float* __restrict__ b1,   // [32]
                        const float* __restrict__ Wt1,  // [32,64]
                        const float* __restrict__ Wr2)  // [16,32]
{
    int t = threadIdx.x;
    int o = t & 31, sl = t >> 5;
    float wt1[64];
    #pragma unroll
    for (int j = 0; j < 64; j++) wt1[j] = Wt1[o * 64 + j];
    float bias = b1[o];
    int oo = o & 15, jb = (o < 16) ? 0 : 16;

    __shared__ float sW2[16 * 33];           // Wr2 [16x32] row stride 33 (FIXED)
    __shared__ float sh1[32][64];
    __shared__ float sh2[32][32];
    for (int i = t; i < 16 * 32; i += 256) sW2[(i >> 5) * 33 + (i & 31)] = Wr2[i];
    __syncthreads();

    for (int nbase = blockIdx.x * 32; nbase < N_NODES; nbase += gridDim.x * 32) {
        for (int i = t; i < 512; i += 256) {
            int n2 = i >> 4, r = i & 15;
            int nn = nbase + n2;
            if (nn < N_NODES)
                *(float4*)&sh1[n2][r * 4] = *(const float4*)&g_h1[nn * 64 + r * 4];
        }
        __syncthreads();
        float hq[4];
        #pragma unroll
        for (int q = 0; q < 4; q++) {
            int nl = sl + 8 * q, node = nbase + nl;
            float h = bias;
            if (node < N_NODES) h += g_agg1[node * 32 + o];
            #pragma unroll
            for (int c = 0; c < 16; c++) {
                float4 hv = *(const float4*)&sh1[nl][c * 4];
                h += wt1[4*c+0]*hv.x + wt1[4*c+1]*hv.y + wt1[4*c+2]*hv.z + wt1[4*c+3]*hv.w;
            }
            hq[q] = tanhf(h);
        }
        #pragma unroll
        for (int q = 0; q < 4; q++) {
            int nl = sl + 8 * q, node = nbase + nl;
            if (node < N_NODES) g_h2[node * 32 + o] = hq[q];
            sh2[nl][o] = hq[q];
        }
        __syncwarp();
        #pragma unroll
        for (int q = 0; q < 4; q++) {
            int nl = sl + 8 * q, node = nbase + nl;
            float p = 0.f;
            #pragma unroll
            for (int c = 0; c < 4; c++) {
                float4 hv = *(const float4*)&sh2[nl][jb + c * 4];
                const float* wrow = &sW2[oo * 33 + jb + c * 4];
                p += wrow[0]*hv.x + wrow[1]*hv.y + wrow[2]*hv.z + wrow[3]*hv.w;
            }
            float other = __shfl_down_sync(0xffffffffu, p, 16);
            if (node < N_NODES && o < 16) g_y2[node * 16 + o] = p + other;
        }
        __syncthreads();
    }
}

// ---------------- node kernel 2 + pooling: 64 nodes/iter, ILP=4 -------------
__global__ void k_node2_pool(const int* __restrict__ batch_raw,
                             const float* __restrict__ b2,   // [16]
                             const float* __restrict__ Wt2)  // [16,32]
{
    int t = threadIdx.x;
    int o = t & 15, sl = t >> 4;
    float wt2[32];
    #pragma unroll
    for (int j = 0; j < 32; j++) wt2[j] = Wt2[o * 32 + j];
    float bias = b2[o];
    int b_is64 = g_b_is64;

    __shared__ float sh2[64][32];

    for (int nbase = blockIdx.x * 64; nbase < N_NODES; nbase += gridDim.x * 64) {
        for (int i = t; i < 512; i += 256) {
            int n2 = i >> 3, r = i & 7;
            int nn = nbase + n2;
            if (nn < N_NODES)
                *(float4*)&sh2[n2][r * 4] = *(const float4*)&g_h2[nn * 32 + r * 4];
        }
        __syncthreads();
        #pragma unroll
        for (int q = 0; q < 4; q++) {
            int nl = sl + 16 * q, node = nbase + nl;
            if (node < N_NODES) {
                float acc = bias + g_agg2[node * 16 + o];
                #pragma unroll
                for (int c = 0; c < 8; c++) {
                    float4 hv = *(const float4*)&sh2[nl][c * 4];
                    acc += wt2[4*c+0]*hv.x + wt2[4*c+1]*hv.y + wt2[4*c+2]*hv.z + wt2[4*c+3]*hv.w;
                }
                int g = b_is64 ? batch_raw[2 * node] : batch_raw[node];
                atomicAdd(&g_pool[g * 16 + o], acc);
                if (o == 0) atomicAdd(&g_cnt[g], 1.0f);
            }
        }
        __syncthreads();
    }
}

// ---------------- final: out = tanh(pool / max(cnt,1)) ----------------------
__global__ void k_final(float* __restrict__ out) {
    int t = blockIdx.x * blockDim.x + threadIdx.x;
    if (t < N_GRAPHS * 16) {
        int g = t >> 4;
        out[t] = tanhf(g_pool[t] / fmaxf(g_cnt[g], 1.0f));
    }
}

extern "C" void kernel_launch(void* const* d_in, const int* in_sizes, int n_in,
                              void* d_out, int out_size) {
    const float* x         = (const float*)d_in[0];
    const int*   ei_raw    = (const int*)d_in[1];
    const int*   batch_raw = (const int*)d_in[2];
    const float* Wr0 = (const float*)d_in[3];
    const float* b0  = (const float*)d_in[4];
    const float* Wt0 = (const float*)d_in[5];
    const float* Wr1 = (const float*)d_in[6];
    const float* b1  = (const float*)d_in[7];
    const float* Wt1 = (const float*)d_in[8];
    const float* Wr2 = (const float*)d_in[9];
    const float* b2  = (const float*)d_in[10];
    const float* Wt2 = (const float*)d_in[11];
    float* out = (float*)d_out;

    k_detect<<<1, 1>>>(ei_raw, batch_raw);
    k_prep<<<2048, 256>>>(x, ei_raw);
    k_scatter0<<<(int)(((long long)N_EDGES * 10 + 255) / 256), 256>>>();
    k_node0<<<296, 256>>>(Wr0, b0, Wt0, Wr1);
    k_scatter1<<<(int)(((long long)N_EDGES * 8 + 255) / 256), 256>>>();
    k_node1<<<296, 256>>>(b1, Wt1, Wr2);
    k_scatter2<<<(int)(((long long)N_EDGES * 4 + 255) / 256), 256>>>();
    k_node2_pool<<<296, 256>>>(batch_raw, b2, Wt2);
    k_final<<<16, 256>>>(out);
}